// round 14
// baseline (speedup 1.0000x reference)
#include <cuda_runtime.h>
#include <cstdint>

// CASSI forward — cp.async-staged fused kernel (final consolidated config).
//
//   y2[b,i,k]    = sum_l x[b,l,i,k-2l] * phi[i,k-2l]   (0 <= k-2l < N)
//   out[b,l,i,j] = phi[i,j] * y2[b,i,2l+j]
//
// R14 = measured optimum of each knob across R11/R12/R13:
//   * STAGES=4 ring (best kernel time + DRAM%; 8 stages raised L1 for nothing)
//   * ONE __syncthreads per pipeline iteration (barrier also proves the
//     refill target buffer (l+S-1)%S is free)
//   * non-persistent grid: one CTA per (b,i) row, 4096 CTAs, 8/SM
//   * cp.async.cg 16B (no register residency, L1 bypass, perfectly coalesced)
//   * conflict-free float2 smem epilogue + coalesced streaming stores
//
// Plateau note: six structurally distinct designs all converge to
// ~5.5 TB/s mixed-stream HBM — this sits at the measured best corner.

#define B_      8
#define L_      28
#define M_      512
#define N_      512
#define STRIDE_ 2
#define NOUT_   (N_ + STRIDE_ * (L_ - 1))   // 566
#define TPB     256
#define STAGES  4

__device__ __forceinline__ void cp_async16(uint32_t smem_dst, const void* gptr) {
    asm volatile("cp.async.cg.shared.global [%0], [%1], 16;\n"
                 :: "r"(smem_dst), "l"(gptr));
}
__device__ __forceinline__ void cp_commit() {
    asm volatile("cp.async.commit_group;\n");
}

__global__ __launch_bounds__(TPB) void cassi_cpasync_kernel(
    const float* __restrict__ x,
    const float* __restrict__ phi,
    float* __restrict__ out)
{
    __shared__ __align__(16) float phi_s[N_];
    __shared__ __align__(16) float y2_s[NOUT_ + 2];
    __shared__ __align__(16) float xs[STAGES][N_];

    const int bm = blockIdx.x;            // (b, i)
    const int b  = bm >> 9;
    const int i  = bm & (M_ - 1);
    const int t  = threadIdx.x;

    const size_t band = (size_t)M_ * N_;
    const float* xb = x + (size_t)b * (L_ * M_ * N_) + (size_t)i * N_;
    const uint32_t xs_base = (uint32_t)__cvta_generic_to_shared(&xs[0][0]);

    // phi row i -> smem (published by the first pipeline barrier)
    if (t < N_ / 4) {
        const float4* p4 = reinterpret_cast<const float4*>(phi + (size_t)i * N_);
        reinterpret_cast<float4*>(phi_s)[t] = p4[t];
    }

    // ---- prologue: fill S-1 stages (one commit per stage) ----
    #pragma unroll
    for (int s = 0; s < STAGES - 1; ++s) {
        if (t < N_ / 4)
            cp_async16(xs_base + (uint32_t)(s * N_ + t * 4) * 4,
                       xb + (size_t)s * band + t * 4);
        cp_commit();
    }

    float a0 = 0.f, a1 = 0.f, a2 = 0.f;

    // ---- main pipeline: ONE barrier per iteration ----
    #pragma unroll
    for (int l = 0; l < L_; ++l) {
        asm volatile("cp.async.wait_group %0;\n" :: "n"(STAGES - 2));
        __syncthreads();   // stage l visible; buffer (l+S-1)%S proven free

        const float* xr = xs[l % STAGES];

        const int n1 = t + TPB - STRIDE_ * l;          // always in [202,511]
        a1 += xr[n1] * phi_s[n1];
        if (t >= STRIDE_ * l) {
            const int n0 = t - STRIDE_ * l;            // stream k0 = t
            a0 += xr[n0] * phi_s[n0];
        } else {
            const int n2 = t + 2 * TPB - STRIDE_ * l;  // stream k2 (t < 54)
            a2 += xr[n2] * phi_s[n2];
        }

        if (l + STAGES - 1 < L_) {
            if (t < N_ / 4)
                cp_async16(xs_base +
                           (uint32_t)(((l + STAGES - 1) % STAGES) * N_ + t * 4) * 4,
                           xb + (size_t)(l + STAGES - 1) * band + t * 4);
        }
        cp_commit();       // real or empty: keeps wait arithmetic uniform
    }

    // ---- stage y2 ----
    y2_s[t] = a0;
    y2_s[t + TPB] = a1;
    if (t < NOUT_ - 2 * TPB) y2_s[t + 2 * TPB] = a2;   // t < 54
    __syncthreads();

    // ---- epilogue: thread t -> output columns j = {2t, 2t+1};
    //      y2 word offset 2l+2t == float2 index (l+t): conflict-free LDS.64 ----
    const float2 phi_reg = reinterpret_cast<const float2*>(phi_s)[t];
    float* ob = out + (size_t)b * (L_ * M_ * N_) + (size_t)i * N_ + 2 * t;

    #pragma unroll
    for (int l = 0; l < L_; ++l) {
        float2 yv = reinterpret_cast<const float2*>(y2_s)[l + t];
        float2 r;
        r.x = phi_reg.x * yv.x;
        r.y = phi_reg.y * yv.y;
        __stcs(reinterpret_cast<float2*>(ob + (size_t)l * band), r);
    }
}

extern "C" void kernel_launch(void* const* d_in, const int* in_sizes, int n_in,
                              void* d_out, int out_size)
{
    const float* x   = (const float*)d_in[0];
    const float* phi = (const float*)d_in[1];
    float* out       = (float*)d_out;

    cassi_cpasync_kernel<<<B_ * M_, TPB>>>(x, phi, out);
}

// round 15
// speedup vs baseline: 1.0589x; 1.0589x over previous
#include <cuda_runtime.h>
#include <cstdint>

// CASSI forward — cp.async-staged fused kernel (FINAL, converged config = R13).
//
//   y2[b,i,k]    = sum_l x[b,l,i,k-2l] * phi[i,k-2l]   (0 <= k-2l < N)
//   out[b,l,i,j] = phi[i,j] * y2[b,i,2l+j]
//
// Convergence evidence: six structurally distinct designs (scalar-LDG,
// hybrid, wide-CTA, cp.async x{4,8} stages, persistent) all land at
// 74.0-75.7us kernel / ~5.5 TB/s — the mixed read/write HBM ceiling for
// this footprint (pure-write peaks at 58%, pure-read ~85%; harmonic mix
// ~70% matches). Config below had the best measured end-to-end bench.
//
//   * one CTA per (b,i) row: 4096 CTAs, TPB=256, 8 CTAs/SM, regs=32
//   * 8-stage cp.async.cg ring (16B, L1-bypass, perfectly coalesced,
//     MLP decoupled from the register budget)
//   * ONE __syncthreads per pipeline iteration (the iteration-top barrier
//     both publishes stage l and proves refill target (l+S-1)%S is free)
//   * 3 accumulation streams/thread; exactly 2 active per band (k0/k2
//     validity is complementary), k1 unpredicated
//   * conflict-free float2 smem epilogue + coalesced streaming stores

#define B_      8
#define L_      28
#define M_      512
#define N_      512
#define STRIDE_ 2
#define NOUT_   (N_ + STRIDE_ * (L_ - 1))   // 566
#define TPB     256
#define STAGES  8

__device__ __forceinline__ void cp_async16(uint32_t smem_dst, const void* gptr) {
    asm volatile("cp.async.cg.shared.global [%0], [%1], 16;\n"
                 :: "r"(smem_dst), "l"(gptr));
}
__device__ __forceinline__ void cp_commit() {
    asm volatile("cp.async.commit_group;\n");
}

__global__ __launch_bounds__(TPB) void cassi_cpasync_kernel(
    const float* __restrict__ x,
    const float* __restrict__ phi,
    float* __restrict__ out)
{
    __shared__ __align__(16) float phi_s[N_];
    __shared__ __align__(16) float y2_s[NOUT_ + 2];
    __shared__ __align__(16) float xs[STAGES][N_];

    const int bm = blockIdx.x;            // (b, i)
    const int b  = bm >> 9;
    const int i  = bm & (M_ - 1);
    const int t  = threadIdx.x;

    const size_t band = (size_t)M_ * N_;
    const float* xb = x + (size_t)b * (L_ * M_ * N_) + (size_t)i * N_;
    const uint32_t xs_base = (uint32_t)__cvta_generic_to_shared(&xs[0][0]);

    // phi row i -> smem (published by the first pipeline barrier)
    if (t < N_ / 4) {
        const float4* p4 = reinterpret_cast<const float4*>(phi + (size_t)i * N_);
        reinterpret_cast<float4*>(phi_s)[t] = p4[t];
    }

    // ---- prologue: fill S-1 stages (one commit per stage) ----
    #pragma unroll
    for (int s = 0; s < STAGES - 1; ++s) {
        if (t < N_ / 4)
            cp_async16(xs_base + (uint32_t)(s * N_ + t * 4) * 4,
                       xb + (size_t)s * band + t * 4);
        cp_commit();
    }

    float a0 = 0.f, a1 = 0.f, a2 = 0.f;

    // ---- main pipeline: ONE barrier per iteration ----
    #pragma unroll
    for (int l = 0; l < L_; ++l) {
        asm volatile("cp.async.wait_group %0;\n" :: "n"(STAGES - 2));
        __syncthreads();   // stage l visible; buffer (l+S-1)%S proven free

        const float* xr = xs[l % STAGES];

        const int n1 = t + TPB - STRIDE_ * l;          // always in [202,511]
        a1 += xr[n1] * phi_s[n1];
        if (t >= STRIDE_ * l) {
            const int n0 = t - STRIDE_ * l;            // stream k0 = t
            a0 += xr[n0] * phi_s[n0];
        } else {
            const int n2 = t + 2 * TPB - STRIDE_ * l;  // stream k2 (t < 54)
            a2 += xr[n2] * phi_s[n2];
        }

        if (l + STAGES - 1 < L_) {
            if (t < N_ / 4)
                cp_async16(xs_base +
                           (uint32_t)(((l + STAGES - 1) % STAGES) * N_ + t * 4) * 4,
                           xb + (size_t)(l + STAGES - 1) * band + t * 4);
        }
        cp_commit();       // real or empty: keeps wait arithmetic uniform
    }

    // ---- stage y2 ----
    y2_s[t] = a0;
    y2_s[t + TPB] = a1;
    if (t < NOUT_ - 2 * TPB) y2_s[t + 2 * TPB] = a2;   // t < 54
    __syncthreads();

    // ---- epilogue: thread t -> output columns j = {2t, 2t+1};
    //      y2 word offset 2l+2t == float2 index (l+t): conflict-free LDS.64 ----
    const float2 phi_reg = reinterpret_cast<const float2*>(phi_s)[t];
    float* ob = out + (size_t)b * (L_ * M_ * N_) + (size_t)i * N_ + 2 * t;

    #pragma unroll
    for (int l = 0; l < L_; ++l) {
        float2 yv = reinterpret_cast<const float2*>(y2_s)[l + t];
        float2 r;
        r.x = phi_reg.x * yv.x;
        r.y = phi_reg.y * yv.y;
        __stcs(reinterpret_cast<float2*>(ob + (size_t)l * band), r);
    }
}

extern "C" void kernel_launch(void* const* d_in, const int* in_sizes, int n_in,
                              void* d_out, int out_size)
{
    const float* x   = (const float*)d_in[0];
    const float* phi = (const float*)d_in[1];
    float* out       = (float*)d_out;

    cassi_cpasync_kernel<<<B_ * M_, TPB>>>(x, phi, out);
}